// round 8
// baseline (speedup 1.0000x reference)
#include <cuda_runtime.h>
#include <cstdint>

// HighOrderFactorizationMachineModel: BATCH=16384, F=20, EMBED_DIM=16, ORDER=3.
// emb row = 32 floats: [0:16) order-2 dims, [16:32) order-3 dims.
// Closed forms via power sums: e2=(p1^2-p2)/2, e3=(p1^3-3p1p2+2p3)/6.
//
// R8 = R7 with the LEGAL evict-last encoding: sm_103a ptxas rejects the
// inline .L2::evict_last on scalar ld; the supported form is createpolicy
// (fractional evict_last 1.0) + ld.global.nc.L2::cache_hint. Goal: pin the
// ~36MB gather working set in L2 across graph replays (timed runs were only
// 17% faster than cold -> no L2 retention today).

#define FM_BATCH 16384
#define FM_F 20
#define FM_FIELD_DIM 50000

__global__ __launch_bounds__(256)
void fm_ho_kernel(const int* __restrict__ x,
                  const float* __restrict__ emb,
                  const float* __restrict__ lin,
                  const float* __restrict__ bias,
                  float* __restrict__ out)
{
    const int warp = (blockIdx.x * blockDim.x + threadIdx.x) >> 5;
    const int lane = threadIdx.x & 31;
    const int s = warp;

    // Evict-last access policy (covers full line lifetime in L2).
    uint64_t pol;
    asm("createpolicy.fractional.L2::evict_last.b64 %0, 1.0;" : "=l"(pol));

    // Index row: 20 ints = 80B, 16B-aligned -> 5x int4 (broadcast, L1-friendly).
    int idx[FM_F];
    {
        const int4* xr = (const int4*)(x + s * FM_F);
        #pragma unroll
        for (int q = 0; q < FM_F / 4; q++) {
            const int4 t = __ldg(&xr[q]);
            idx[4 * q + 0] = t.x + (4 * q + 0) * FM_FIELD_DIM;
            idx[4 * q + 1] = t.y + (4 * q + 1) * FM_FIELD_DIM;
            idx[4 * q + 2] = t.z + (4 * q + 2) * FM_FIELD_DIM;
            idx[4 * q + 3] = t.w + (4 * q + 3) * FM_FIELD_DIM;
        }
    }

    // Lin gather rides on lanes 0..19, issued before the emb gathers so it
    // overlaps them; evict-last to keep lin sectors resident.
    float linv = 0.0f;
    if (lane < FM_F) {
        const float* p = lin + idx[lane];
        asm("ld.global.nc.L2::cache_hint.f32 %0, [%1], %2;"
            : "=f"(linv) : "l"(p), "l"(pol));
    }

    // 20 emb gathers, one coalesced 128B line each (lane l owns element l),
    // evict-last to pin the working set in L2 across replays.
    float v[FM_F];
    #pragma unroll
    for (int f = 0; f < FM_F; f++) {
        const float* p = emb + (long)idx[f] * 32 + lane;
        asm("ld.global.nc.L2::cache_hint.f32 %0, [%1], %2;"
            : "=f"(v[f]) : "l"(p), "l"(pol));
    }

    // Power sums.
    float p1 = 0.0f, p2 = 0.0f, p3 = 0.0f;
    #pragma unroll
    for (int f = 0; f < FM_F; f++) {
        const float w = v[f];
        const float w2 = w * w;
        p1 += w;
        p2 += w2;
        p3 += w2 * w;
    }

    // Lanes 0..15: order-2 dims. Lanes 16..31: order-3 dims.
    float term;
    if (lane < 16) {
        term = 0.5f * (p1 * p1 - p2);
    } else {
        term = (p1 * p1 * p1 - 3.0f * p1 * p2 + 2.0f * p3) * (1.0f / 6.0f);
    }
    term += linv;   // lanes 0..19 contribute linear part, others add 0

    // Warp-wide sum.
    #pragma unroll
    for (int o = 16; o > 0; o >>= 1)
        term += __shfl_xor_sync(0xffffffffu, term, o);

    if (lane == 0)
        out[s] = term + __ldg(&bias[0]);
}

extern "C" void kernel_launch(void* const* d_in, const int* in_sizes, int n_in,
                              void* d_out, int out_size)
{
    const int*   x    = (const int*)d_in[0];
    const float* emb  = (const float*)d_in[1];
    const float* lin  = (const float*)d_in[2];
    const float* bias = (const float*)d_in[3];
    float*       out  = (float*)d_out;

    // 16384 samples, 1 warp each, 8 warps/block -> 2048 blocks.
    const int threads = 256;
    const int blocks  = (FM_BATCH * 32) / threads;
    fm_ho_kernel<<<blocks, threads>>>(x, emb, lin, bias, out);
}

// round 9
// speedup vs baseline: 1.0173x; 1.0173x over previous
#include <cuda_runtime.h>
#include <cstdint>

// HighOrderFactorizationMachineModel: BATCH=16384, F=20, EMBED_DIM=16, ORDER=3.
// emb row = 32 floats: [0:16) order-2 dims, [16:32) order-3 dims.
// Closed forms via power sums: e2=(p1^2-p2)/2, e3=(p1^3-3p1p2+2p3)/6.
//
// R9: split L2 eviction policy. R8 (evict_last on everything) regressed 40%,
// proving the eviction knob is on the critical path but "pin all 40MB" thrashes
// the set-aside partition. This round: fields 0..9 emb (18MB unique) stay
// evict-NORMAL (protected residents), while fields 10..19 emb + all lin
// gathers (the worst pollution: 327k scattered 32B sectors) are marked
// evict_FIRST so they stream through without displacing the protected half.

#define FM_BATCH 16384
#define FM_F 20
#define FM_FIELD_DIM 50000

__global__ __launch_bounds__(256)
void fm_ho_kernel(const int* __restrict__ x,
                  const float* __restrict__ emb,
                  const float* __restrict__ lin,
                  const float* __restrict__ bias,
                  float* __restrict__ out)
{
    const int warp = (blockIdx.x * blockDim.x + threadIdx.x) >> 5;
    const int lane = threadIdx.x & 31;
    const int s = warp;

    // Streaming policy: these accesses are first in line for eviction.
    uint64_t pol;
    asm("createpolicy.fractional.L2::evict_first.b64 %0, 1.0;" : "=l"(pol));

    // Index row: 20 ints = 80B, 16B-aligned -> 5x int4 (broadcast loads).
    int idx[FM_F];
    {
        const int4* xr = (const int4*)(x + s * FM_F);
        #pragma unroll
        for (int q = 0; q < FM_F / 4; q++) {
            const int4 t = __ldg(&xr[q]);
            idx[4 * q + 0] = t.x + (4 * q + 0) * FM_FIELD_DIM;
            idx[4 * q + 1] = t.y + (4 * q + 1) * FM_FIELD_DIM;
            idx[4 * q + 2] = t.z + (4 * q + 2) * FM_FIELD_DIM;
            idx[4 * q + 3] = t.w + (4 * q + 3) * FM_FIELD_DIM;
        }
    }

    // Lin gather (lanes 0..19): scattered 4B values -> pure pollution, stream it.
    float linv = 0.0f;
    if (lane < FM_F) {
        const float* p = lin + idx[lane];
        asm("ld.global.nc.L2::cache_hint.f32 %0, [%1], %2;"
            : "=f"(linv) : "l"(p), "l"(pol));
    }

    // Emb gathers: one coalesced 128B line each (lane l owns element l).
    // Fields 0..9: evict-normal (protected). Fields 10..19: evict_first.
    float v[FM_F];
    #pragma unroll
    for (int f = 0; f < 10; f++)
        v[f] = __ldg(&emb[(long)idx[f] * 32 + lane]);
    #pragma unroll
    for (int f = 10; f < FM_F; f++) {
        const float* p = emb + (long)idx[f] * 32 + lane;
        asm("ld.global.nc.L2::cache_hint.f32 %0, [%1], %2;"
            : "=f"(v[f]) : "l"(p), "l"(pol));
    }

    // Power sums.
    float p1 = 0.0f, p2 = 0.0f, p3 = 0.0f;
    #pragma unroll
    for (int f = 0; f < FM_F; f++) {
        const float w = v[f];
        const float w2 = w * w;
        p1 += w;
        p2 += w2;
        p3 += w2 * w;
    }

    // Lanes 0..15: order-2 dims. Lanes 16..31: order-3 dims.
    float term;
    if (lane < 16) {
        term = 0.5f * (p1 * p1 - p2);
    } else {
        term = (p1 * p1 * p1 - 3.0f * p1 * p2 + 2.0f * p3) * (1.0f / 6.0f);
    }
    term += linv;   // lanes 0..19 contribute linear part, others add 0

    // Warp-wide sum.
    #pragma unroll
    for (int o = 16; o > 0; o >>= 1)
        term += __shfl_xor_sync(0xffffffffu, term, o);

    if (lane == 0)
        out[s] = term + __ldg(&bias[0]);
}

extern "C" void kernel_launch(void* const* d_in, const int* in_sizes, int n_in,
                              void* d_out, int out_size)
{
    const int*   x    = (const int*)d_in[0];
    const float* emb  = (const float*)d_in[1];
    const float* lin  = (const float*)d_in[2];
    const float* bias = (const float*)d_in[3];
    float*       out  = (float*)d_out;

    // 16384 samples, 1 warp each, 8 warps/block -> 2048 blocks.
    const int threads = 256;
    const int blocks  = (FM_BATCH * 32) / threads;
    fm_ho_kernel<<<blocks, threads>>>(x, emb, lin, bias, out);
}